// round 4
// baseline (speedup 1.0000x reference)
#include <cuda_runtime.h>
#include <cstdint>
#include <mma.h>
#include <math.h>

using namespace nvcuda;

#define T_TOK 4096
#define HDIM  2048
#define IDIM  4096
#define NEXP  8
#define TOPK  4
#define CAP   4096

// ---------------- scratch (device globals: allocation-free) ----------------
__device__ int   g_counts[NEXP];
__device__ int   g_tok[NEXP * CAP];
__device__ int   g_slot_epos[T_TOK * TOPK];
__device__ float g_slot_gate[T_TOK * TOPK];
__device__ float g_h1[(size_t)NEXP * CAP * IDIM];
__device__ float g_h2[(size_t)NEXP * CAP * IDIM];
__device__ float g_y [(size_t)NEXP * CAP * HDIM];

// ---------------- init ------------------------------------------------------
__global__ void init_kernel() {
    if (threadIdx.x < NEXP) g_counts[threadIdx.x] = 0;
}

// ---------------- router: 1 warp per token ----------------------------------
__global__ void router_kernel(const float* __restrict__ x,
                              const float* __restrict__ rw) {
    int gtid = blockIdx.x * blockDim.x + threadIdx.x;
    int tok  = gtid >> 5;
    int lane = gtid & 31;
    if (tok >= T_TOK) return;

    const float* xr = x + (size_t)tok * HDIM;
    float acc[NEXP];
#pragma unroll
    for (int e = 0; e < NEXP; e++) acc[e] = 0.f;

    for (int h = lane; h < HDIM; h += 32) {
        float xv = xr[h];
        const float* r = rw + (size_t)h * NEXP;
#pragma unroll
        for (int e = 0; e < NEXP; e++) acc[e] = fmaf(xv, r[e], acc[e]);
    }
#pragma unroll
    for (int off = 16; off; off >>= 1)
#pragma unroll
        for (int e = 0; e < NEXP; e++)
            acc[e] += __shfl_down_sync(0xffffffffu, acc[e], off);

    if (lane == 0) {
        float mx = acc[0];
#pragma unroll
        for (int e = 1; e < NEXP; e++) mx = fmaxf(mx, acc[e]);
        float p[NEXP];
#pragma unroll
        for (int e = 0; e < NEXP; e++) p[e] = acc[e];

        int   sel[TOPK];
        float g[TOPK];
        float s = 0.f;
#pragma unroll
        for (int k = 0; k < TOPK; k++) {
            int best = 0; float bv = -INFINITY;
#pragma unroll
            for (int e = 0; e < NEXP; e++)
                if (p[e] > bv) { bv = p[e]; best = e; }
            sel[k] = best;
            g[k]   = expf(bv - mx);
            s     += g[k];
            p[best] = -INFINITY;
        }
        float inv = 1.f / s;
#pragma unroll
        for (int k = 0; k < TOPK; k++) {
            int e   = sel[k];
            int pos = atomicAdd(&g_counts[e], 1);
            g_tok[e * CAP + pos]        = tok;
            g_slot_epos[tok * TOPK + k] = e * CAP + pos;
            g_slot_gate[tok * TOPK + k] = g[k] * inv;
        }
    }
}

// ---------------- pipelined grouped GEMM (tf32 WMMA) -------------------------
// BM=256, BN=128, BK=32; 8 warps, 64x64 warp tiles; 4-stage cp.async pipeline.
#define BM 256
#define BN 128
#define BK 32
#define STAGES 4
#define LDA 36
#define LDB 132
#define A_STAGE (BM * LDA)
#define B_STAGE (BK * LDB)

__device__ __forceinline__ void cp16(float* smem_ptr, const float* gptr) {
    unsigned int s = (unsigned int)__cvta_generic_to_shared(smem_ptr);
    asm volatile("cp.async.cg.shared.global [%0], [%1], 16;\n" :: "r"(s), "l"(gptr));
}
__device__ __forceinline__ void cp_commit() {
    asm volatile("cp.async.commit_group;\n");
}

template<int PHASE>
__global__ void __launch_bounds__(256)
gemm_kernel(const float* __restrict__ x, const float* __restrict__ W) {
    constexpr int  K    = (PHASE == 0) ? HDIM : IDIM;
    constexpr int  N    = (PHASE == 2) ? HDIM : IDIM;
    constexpr int  KT   = K / BK;
    constexpr bool GATH = (PHASE == 0);
    constexpr bool SILU = (PHASE < 2);

    extern __shared__ float dyn[];
    float* sA   = dyn;
    float* sB   = dyn + STAGES * A_STAGE;
    int*   srow = (int*)(dyn + STAGES * (A_STAGE + B_STAGE));

    const int e       = blockIdx.z;
    const int n_e     = g_counts[e];
    const int rowBase = blockIdx.y * BM;
    if (rowBase >= n_e) return;
    const int colBase = blockIdx.x * BN;
    const int tid     = threadIdx.x;

    {   // row gather table (256 threads == BM rows)
        int r  = rowBase + tid;
        int rr = (r < n_e) ? r : rowBase;
        srow[tid] = GATH ? g_tok[e * CAP + rr] : rr;
    }
    __syncthreads();

    const float* A;
    float* C;
    if (PHASE == 0)      { A = x;                             C = g_h1 + (size_t)e * CAP * IDIM; }
    else if (PHASE == 1) { A = g_h1 + (size_t)e * CAP * IDIM; C = g_h2 + (size_t)e * CAP * IDIM; }
    else                 { A = g_h2 + (size_t)e * CAP * IDIM; C = g_y  + (size_t)e * CAP * HDIM; }
    const float* B = W + (size_t)e * K * N;

    // per-thread load coords
    const float* aSrcRow = A + (size_t)srow[tid] * K;     // this thread always loads row `tid`
    const int bk  = tid >> 5;            // 0..7
    const int bc  = (tid & 31) * 4;      // 0..124

    // warp mapping: 4 x 2 warps of 64x64
    const int warpId = tid >> 5;
    const int wm = (warpId >> 1) * 64;
    const int wn = (warpId & 1)  * 64;
    const int lane = tid & 31;

    wmma::fragment<wmma::accumulator, 16, 16, 8, float> acc[4][4];
#pragma unroll
    for (int i = 0; i < 4; i++)
#pragma unroll
        for (int j = 0; j < 4; j++) wmma::fill_fragment(acc[i][j], 0.f);

#define LOAD_STAGE(st, kt_)                                                        \
    {                                                                              \
        const int k0_ = (kt_) * BK;                                                \
        float* dA = sA + (st) * A_STAGE + tid * LDA;                               \
        const float* sAg = aSrcRow + k0_;                                          \
        _Pragma("unroll")                                                          \
        for (int sg = 0; sg < 8; sg++) cp16(dA + sg * 4, sAg + sg * 4);            \
        _Pragma("unroll")                                                          \
        for (int p = 0; p < 4; p++) {                                              \
            int kk_ = bk + p * 8;                                                  \
            cp16(sB + (st) * B_STAGE + kk_ * LDB + bc,                             \
                 B + (size_t)(k0_ + kk_) * N + colBase + bc);                      \
        }                                                                          \
    }

    // prologue: fill STAGES-1 stages
#pragma unroll
    for (int s = 0; s < STAGES - 1; s++) { LOAD_STAGE(s, s); cp_commit(); }

    for (int kt = 0; kt < KT; kt++) {
        asm volatile("cp.async.wait_group %0;\n" :: "n"(STAGES - 2));
        __syncthreads();

        int nk = kt + STAGES - 1;
        if (nk < KT) LOAD_STAGE(nk % STAGES, nk);
        cp_commit();                    // commit every iter (possibly empty) to keep count math

        const float* a0 = sA + (kt % STAGES) * A_STAGE + wm * LDA;
        const float* b0 = sB + (kt % STAGES) * B_STAGE + wn;
#pragma unroll
        for (int kk = 0; kk < BK; kk += 8) {
            wmma::fragment<wmma::matrix_a, 16, 16, 8, wmma::precision::tf32, wmma::row_major> af[4];
            wmma::fragment<wmma::matrix_b, 16, 16, 8, wmma::precision::tf32, wmma::row_major> bf[4];
#pragma unroll
            for (int i = 0; i < 4; i++) {
                wmma::load_matrix_sync(af[i], a0 + i * 16 * LDA + kk, LDA);
#pragma unroll
                for (int t = 0; t < af[i].num_elements; t++)
                    af[i].x[t] = wmma::__float_to_tf32(af[i].x[t]);
            }
#pragma unroll
            for (int j = 0; j < 4; j++) {
                wmma::load_matrix_sync(bf[j], b0 + kk * LDB + j * 16, LDB);
#pragma unroll
                for (int t = 0; t < bf[j].num_elements; t++)
                    bf[j].x[t] = wmma::__float_to_tf32(bf[j].x[t]);
            }
#pragma unroll
            for (int i = 0; i < 4; i++)
#pragma unroll
                for (int j = 0; j < 4; j++)
                    wmma::mma_sync(acc[i][j], af[i], bf[j], acc[i][j]);
        }
    }
    __syncthreads();    // pipeline done; smem reusable for partial-tile staging

    // epilogue: SiLU on fragments, then store
#pragma unroll
    for (int i = 0; i < 4; i++)
#pragma unroll
        for (int j = 0; j < 4; j++) {
            if (SILU) {
#pragma unroll
                for (int t = 0; t < acc[i][j].num_elements; t++) {
                    float v = acc[i][j].x[t];
                    acc[i][j].x[t] = v / (1.f + expf(-v));
                }
            }
            int fr = rowBase + wm + i * 16;
            float* cdst = C + (size_t)fr * N + colBase + wn + j * 16;
            if (fr + 16 <= n_e) {
                wmma::store_matrix_sync(cdst, acc[i][j], N, wmma::mem_row_major);
            } else if (fr < n_e) {
                float* wstage = dyn + warpId * (16 * 20);
                wmma::store_matrix_sync(wstage, acc[i][j], 20, wmma::mem_row_major);
                __syncwarp();
                int r0 = lane >> 4;       // 0..1
                int c  = lane & 15;
                for (int r = r0; r < 16; r += 2) {
                    if (fr + r < n_e)
                        C[(size_t)(fr + r) * N + colBase + wn + j * 16 + c] =
                            wstage[r * 20 + c];
                }
                __syncwarp();
            }
        }
}

// ---------------- deterministic combine -------------------------------------
__global__ void combine_kernel(float* __restrict__ out) {
    int idx   = blockIdx.x * blockDim.x + threadIdx.x;
    int total = T_TOK * (HDIM / 4);
    if (idx >= total) return;
    int t  = idx / (HDIM / 4);
    int h4 = (idx % (HDIM / 4)) * 4;

    float4 s = make_float4(0.f, 0.f, 0.f, 0.f);
#pragma unroll
    for (int k = 0; k < TOPK; k++) {
        int   ep = g_slot_epos[t * TOPK + k];
        float gk = g_slot_gate[t * TOPK + k];
        float4 y = *(const float4*)(g_y + (size_t)ep * HDIM + h4);
        s.x += gk * y.x; s.y += gk * y.y; s.z += gk * y.z; s.w += gk * y.w;
    }
    *(float4*)(out + (size_t)t * HDIM + h4) = s;
}

// ---------------- launch -----------------------------------------------------
extern "C" void kernel_launch(void* const* d_in, const int* in_sizes, int n_in,
                              void* d_out, int out_size) {
    const float* x  = (const float*)d_in[0];
    const float* rw = (const float*)d_in[1];
    const float* w1 = (const float*)d_in[2];
    const float* w2 = (const float*)d_in[3];
    const float* w3 = (const float*)d_in[4];
    float* out = (float*)d_out;

    const int smemBytes = STAGES * (A_STAGE + B_STAGE) * 4 + BM * 4;  // ~212 KB
    cudaFuncSetAttribute(gemm_kernel<0>, cudaFuncAttributeMaxDynamicSharedMemorySize, smemBytes);
    cudaFuncSetAttribute(gemm_kernel<1>, cudaFuncAttributeMaxDynamicSharedMemorySize, smemBytes);
    cudaFuncSetAttribute(gemm_kernel<2>, cudaFuncAttributeMaxDynamicSharedMemorySize, smemBytes);

    init_kernel<<<1, 32>>>();
    router_kernel<<<(T_TOK * 32) / 128, 128>>>(x, rw);

    dim3 blk(256);
    gemm_kernel<0><<<dim3(IDIM / BN, CAP / BM, NEXP), blk, smemBytes>>>(x, w1);
    gemm_kernel<1><<<dim3(IDIM / BN, CAP / BM, NEXP), blk, smemBytes>>>(x, w2);
    gemm_kernel<2><<<dim3(HDIM / BN, CAP / BM, NEXP), blk, smemBytes>>>(x, w3);

    combine_kernel<<<(T_TOK * (HDIM / 4) + 255) / 256, 256>>>(out);
}

// round 7
// speedup vs baseline: 5.3564x; 5.3564x over previous
#include <cuda_runtime.h>
#include <cuda_fp16.h>
#include <cstdint>
#include <mma.h>
#include <math.h>

using namespace nvcuda;

#define T_TOK 4096
#define HDIM  2048
#define IDIM  4096
#define NEXP  8
#define TOPK  4
#define CAP   4096

// GEMM tiling
#define BM 128
#define BN 128
#define BK 64
#define NST 3
#define LDAH 72                    // halves (64 + 8 pad) -> 144B rows
#define LDBH 136                   // halves (128 + 8 pad) -> 272B rows
#define A_ST (BM * LDAH)           // halves
#define B_ST (BK * LDBH)           // halves
#define ST_H (A_ST + B_ST)         // halves per stage
#define LDC  132                   // fp32 epilogue stage stride
#define SMEM_REQ (NST * ST_H * 2 + 512)

// ---------------- scratch (device globals: allocation-free) ------------------
__device__ int    g_counts[NEXP];
__device__ int    g_tok[NEXP * CAP];
__device__ int    g_slot_epos[T_TOK * TOPK];
__device__ float  g_slot_gate[T_TOK * TOPK];
__device__ __half g_xh [(size_t)T_TOK * HDIM];
__device__ __half g_w1h[(size_t)NEXP * HDIM * IDIM];
__device__ __half g_w2h[(size_t)NEXP * IDIM * IDIM];
__device__ __half g_w3h[(size_t)NEXP * IDIM * HDIM];
__device__ __half g_h1 [(size_t)NEXP * CAP * IDIM];
__device__ __half g_h2 [(size_t)NEXP * CAP * IDIM];
__device__ __half g_y  [(size_t)NEXP * CAP * HDIM];

// ---------------- helpers ----------------------------------------------------
__device__ __forceinline__ void cp16(void* smem_ptr, const void* gptr) {
    unsigned int s = (unsigned int)__cvta_generic_to_shared(smem_ptr);
    asm volatile("cp.async.cg.shared.global [%0], [%1], 16;" :: "r"(s), "l"(gptr));
}
__device__ __forceinline__ void cp_commit() {
    asm volatile("cp.async.commit_group;");
}

// ---------------- init / fp32->fp16 convert ---------------------------------
__global__ void init_kernel() {
    if (threadIdx.x < NEXP) g_counts[threadIdx.x] = 0;
}

__global__ void cvt_kernel(const float4* __restrict__ src,
                           __half2* __restrict__ dst, int n4) {
    int i = blockIdx.x * blockDim.x + threadIdx.x;
    if (i >= n4) return;
    float4 v = src[i];
    dst[2 * i]     = __floats2half2_rn(v.x, v.y);
    dst[2 * i + 1] = __floats2half2_rn(v.z, v.w);
}

// ---------------- router: 1 warp per token (fp32, matches reference) ---------
__global__ void router_kernel(const float* __restrict__ x,
                              const float* __restrict__ rw) {
    int gtid = blockIdx.x * blockDim.x + threadIdx.x;
    int tok  = gtid >> 5;
    int lane = gtid & 31;
    if (tok >= T_TOK) return;

    const float* xr = x + (size_t)tok * HDIM;
    float acc[NEXP];
#pragma unroll
    for (int e = 0; e < NEXP; e++) acc[e] = 0.f;
    for (int h = lane; h < HDIM; h += 32) {
        float xv = xr[h];
        const float* r = rw + (size_t)h * NEXP;
#pragma unroll
        for (int e = 0; e < NEXP; e++) acc[e] = fmaf(xv, r[e], acc[e]);
    }
#pragma unroll
    for (int off = 16; off; off >>= 1)
#pragma unroll
        for (int e = 0; e < NEXP; e++)
            acc[e] += __shfl_down_sync(0xffffffffu, acc[e], off);

    if (lane == 0) {
        float mx = acc[0];
#pragma unroll
        for (int e = 1; e < NEXP; e++) mx = fmaxf(mx, acc[e]);
        float p[NEXP];
#pragma unroll
        for (int e = 0; e < NEXP; e++) p[e] = acc[e];
        int sel[TOPK]; float g[TOPK]; float s = 0.f;
#pragma unroll
        for (int k = 0; k < TOPK; k++) {
            int best = 0; float bv = -INFINITY;
#pragma unroll
            for (int e = 0; e < NEXP; e++)
                if (p[e] > bv) { bv = p[e]; best = e; }
            sel[k] = best; g[k] = expf(bv - mx); s += g[k]; p[best] = -INFINITY;
        }
        float inv = 1.f / s;
#pragma unroll
        for (int k = 0; k < TOPK; k++) {
            int e = sel[k];
            int pos = atomicAdd(&g_counts[e], 1);
            g_tok[e * CAP + pos]        = tok;
            g_slot_epos[tok * TOPK + k] = e * CAP + pos;
            g_slot_gate[tok * TOPK + k] = g[k] * inv;
        }
    }
}

// ---------------- fp16 pipelined grouped GEMM --------------------------------
// PHASE 0: H1 = silu(gather(Xh) @ W1h)   K=2048 N=4096
// PHASE 1: H2 = silu(H1 @ W2h)           K=4096 N=4096
// PHASE 2: Y  = H2 @ W3h                 K=4096 N=2048
template<int PHASE>
__global__ void __launch_bounds__(128)
gemm_hk(const __half* __restrict__ Wh) {
    constexpr int  K    = (PHASE == 0) ? HDIM : IDIM;
    constexpr int  N    = (PHASE == 2) ? HDIM : IDIM;
    constexpr int  KT   = K / BK;
    constexpr bool GATH = (PHASE == 0);
    constexpr bool SILU = (PHASE < 2);

    const int e       = blockIdx.z;
    const int n_e     = g_counts[e];
    const int rowBase = blockIdx.y * BM;
    if (rowBase >= n_e) return;
    const int colBase = blockIdx.x * BN;
    const int tid     = threadIdx.x;
    const int wid     = tid >> 5;

    extern __shared__ __half sh[];
    int* srow = (int*)(sh + NST * ST_H);

    {
        int r = rowBase + tid;
        if (r >= n_e) r = n_e - 1;
        srow[tid] = GATH ? g_tok[e * CAP + r] : r;
    }
    __syncthreads();

    const __half* Aptr;
    __half* C;
    if (PHASE == 0)      { Aptr = g_xh;                          C = g_h1 + (size_t)e * CAP * IDIM; }
    else if (PHASE == 1) { Aptr = g_h1 + (size_t)e * CAP * IDIM; C = g_h2 + (size_t)e * CAP * IDIM; }
    else                 { Aptr = g_h2 + (size_t)e * CAP * IDIM; C = g_y  + (size_t)e * CAP * HDIM; }
    const __half* Wp = Wh + (size_t)e * K * N;

    // producer coords
    const int am = tid >> 3, aq = tid & 7;     // A: 16 rows x 8 chunks, x8 iters
    const int bk = tid >> 4, bq = tid & 15;    // B: 8 rows x 16 chunks, x8 iters

#define LOAD_STAGE(ST, K0)                                                         \
    {                                                                              \
        __half* dA = sh + (ST) * ST_H;                                             \
        __half* dB = dA + A_ST;                                                    \
        _Pragma("unroll")                                                          \
        for (int i = 0; i < 8; i++) {                                              \
            int m = am + 16 * i;                                                   \
            cp16(dA + m * LDAH + aq * 8,                                           \
                 Aptr + (size_t)srow[m] * K + (K0) + aq * 8);                      \
        }                                                                          \
        _Pragma("unroll")                                                          \
        for (int i = 0; i < 8; i++) {                                              \
            int kk = bk + 8 * i;                                                   \
            cp16(dB + kk * LDBH + bq * 8,                                          \
                 Wp + (size_t)((K0) + kk) * N + colBase + bq * 8);                 \
        }                                                                          \
    }

    const int wr = (wid >> 1) * 64;
    const int wc = (wid & 1)  * 64;

    wmma::fragment<wmma::accumulator, 16, 16, 16, float> acc[4][4];
#pragma unroll
    for (int i = 0; i < 4; i++)
#pragma unroll
        for (int j = 0; j < 4; j++) wmma::fill_fragment(acc[i][j], 0.f);

#pragma unroll
    for (int s = 0; s < NST - 1; s++) { LOAD_STAGE(s, s * BK); cp_commit(); }

    for (int ct = 0; ct < KT; ct++) {
        __syncthreads();                       // stage (ct+NST-1)%NST fully consumed
        int pf = ct + NST - 1;
        if (pf < KT) LOAD_STAGE(pf % NST, pf * BK);
        cp_commit();
        asm volatile("cp.async.wait_group %0;" :: "n"(NST - 2));
        __syncthreads();                       // stage ct visible to all warps

        const __half* a0 = sh + (ct % NST) * ST_H + wr * LDAH;
        const __half* b0 = sh + (ct % NST) * ST_H + A_ST + wc;
#pragma unroll
        for (int kk = 0; kk < BK; kk += 16) {
            wmma::fragment<wmma::matrix_a, 16, 16, 16, half, wmma::row_major> af[4];
            wmma::fragment<wmma::matrix_b, 16, 16, 16, half, wmma::row_major> bf[4];
#pragma unroll
            for (int i = 0; i < 4; i++)
                wmma::load_matrix_sync(af[i], a0 + i * 16 * LDAH + kk, LDAH);
#pragma unroll
            for (int j = 0; j < 4; j++)
                wmma::load_matrix_sync(bf[j], b0 + kk * LDBH + j * 16, LDBH);
#pragma unroll
            for (int i = 0; i < 4; i++)
#pragma unroll
                for (int j = 0; j < 4; j++)
                    wmma::mma_sync(acc[i][j], af[i], bf[j], acc[i][j]);
        }
    }

    // epilogue: stage fp32 in smem, SiLU, convert, half2 stores
    __syncthreads();
    float* sC = (float*)sh;
#pragma unroll
    for (int i = 0; i < 4; i++)
#pragma unroll
        for (int j = 0; j < 4; j++)
            wmma::store_matrix_sync(sC + (wr + i * 16) * LDC + wc + j * 16,
                                    acc[i][j], LDC, wmma::mem_row_major);
    __syncthreads();

    for (int idx = tid; idx < BM * (BN / 2); idx += 128) {
        int row = idx >> 6;
        int cp  = idx & 63;
        int gr  = rowBase + row;
        if (gr < n_e) {
            float f0 = sC[row * LDC + 2 * cp];
            float f1 = sC[row * LDC + 2 * cp + 1];
            if (SILU) {
                f0 = f0 / (1.f + expf(-f0));
                f1 = f1 / (1.f + expf(-f1));
            }
            ((__half2*)(C + (size_t)gr * N + colBase))[cp] = __floats2half2_rn(f0, f1);
        }
    }
}

// ---------------- deterministic combine -------------------------------------
__global__ void combine_kernel(float* __restrict__ out) {
    int idx   = blockIdx.x * blockDim.x + threadIdx.x;
    int total = T_TOK * (HDIM / 2);
    if (idx >= total) return;
    int t  = idx / (HDIM / 2);
    int hp = idx % (HDIM / 2);

    float sx = 0.f, sy = 0.f;
#pragma unroll
    for (int k = 0; k < TOPK; k++) {
        int   ep = g_slot_epos[t * TOPK + k];
        float gk = g_slot_gate[t * TOPK + k];
        __half2 y = ((const __half2*)(g_y + (size_t)ep * HDIM))[hp];
        float2 yf = __half22float2(y);
        sx += gk * yf.x;
        sy += gk * yf.y;
    }
    ((float2*)(out + (size_t)t * HDIM))[hp] = make_float2(sx, sy);
}

// ---------------- launch -----------------------------------------------------
extern "C" void kernel_launch(void* const* d_in, const int* in_sizes, int n_in,
                              void* d_out, int out_size) {
    const float* x  = (const float*)d_in[0];
    const float* rw = (const float*)d_in[1];
    const float* w1 = (const float*)d_in[2];
    const float* w2 = (const float*)d_in[3];
    const float* w3 = (const float*)d_in[4];
    float* out = (float*)d_out;

    cudaFuncSetAttribute(gemm_hk<0>, cudaFuncAttributeMaxDynamicSharedMemorySize, SMEM_REQ);
    cudaFuncSetAttribute(gemm_hk<1>, cudaFuncAttributeMaxDynamicSharedMemorySize, SMEM_REQ);
    cudaFuncSetAttribute(gemm_hk<2>, cudaFuncAttributeMaxDynamicSharedMemorySize, SMEM_REQ);

    init_kernel<<<1, 32>>>();

    // fp32 -> fp16 conversions
    __half *xh, *w1h, *w2h, *w3h;
    cudaGetSymbolAddress((void**)&xh,  g_xh);
    cudaGetSymbolAddress((void**)&w1h, g_w1h);
    cudaGetSymbolAddress((void**)&w2h, g_w2h);
    cudaGetSymbolAddress((void**)&w3h, g_w3h);

    int n4x  = T_TOK * HDIM / 4;
    int n4w1 = NEXP * HDIM * IDIM / 4;
    int n4w2 = NEXP * IDIM * IDIM / 4;
    int n4w3 = NEXP * IDIM * HDIM / 4;
    cvt_kernel<<<(n4x  + 255) / 256, 256>>>((const float4*)x,  (__half2*)xh,  n4x);
    cvt_kernel<<<(n4w1 + 255) / 256, 256>>>((const float4*)w1, (__half2*)w1h, n4w1);
    cvt_kernel<<<(n4w2 + 255) / 256, 256>>>((const float4*)w2, (__half2*)w2h, n4w2);
    cvt_kernel<<<(n4w3 + 255) / 256, 256>>>((const float4*)w3, (__half2*)w3h, n4w3);

    router_kernel<<<(T_TOK * 32) / 128, 128>>>(x, rw);

    dim3 blk(128);
    gemm_hk<0><<<dim3(IDIM / BN, CAP / BM, NEXP), blk, SMEM_REQ>>>(w1h);
    gemm_hk<1><<<dim3(IDIM / BN, CAP / BM, NEXP), blk, SMEM_REQ>>>(w2h);
    gemm_hk<2><<<dim3(HDIM / BN, CAP / BM, NEXP), blk, SMEM_REQ>>>(w3h);

    combine_kernel<<<(T_TOK * (HDIM / 2) + 255) / 256, 256>>>(out);
}